// round 7
// baseline (speedup 1.0000x reference)
#include <cuda_runtime.h>
#include <cuda_bf16.h>
#include <math.h>
#include <stdint.h>

#define BATCH 2
#define SEQL 2048
#define HID 1024
#define NHEAD 16
#define HDIM 64
#define MTOT (BATCH * SEQL)   // 4096

// ---------------------------------------------------------------------------
// Scratch (__device__ globals; allocation-free rule)
// ---------------------------------------------------------------------------
__device__ float g_ctx[MTOT * HID];
__device__ __nv_bfloat16 g_xh[MTOT * HID], g_xl[MTOT * HID];
__device__ __nv_bfloat16 g_qh[MTOT * HID], g_ql[MTOT * HID];
__device__ __nv_bfloat16 g_kh[MTOT * HID], g_kl[MTOT * HID];
__device__ __nv_bfloat16 g_vh[MTOT * HID], g_vl[MTOT * HID];
__device__ __nv_bfloat16 g_ch[MTOT * HID], g_cl[MTOT * HID];
__device__ __nv_bfloat16 g_Wqh[HID * HID], g_Wql[HID * HID];
__device__ __nv_bfloat16 g_Wkh[HID * HID], g_Wkl[HID * HID];
__device__ __nv_bfloat16 g_Wvh[HID * HID], g_Wvl[HID * HID];
__device__ __nv_bfloat16 g_Woh[HID * HID], g_Wol[HID * HID];

// ---------------------------------------------------------------------------
// PTX helpers (arch-neutral: ldmatrix / mma.sync / cp.async only)
// ---------------------------------------------------------------------------
__device__ __forceinline__ uint32_t smem_u32(const void* p) {
  uint32_t a;
  asm("{ .reg .u64 t; cvta.to.shared.u64 t, %1; cvt.u32.u64 %0, t; }"
      : "=r"(a) : "l"(p));
  return a;
}

__device__ __forceinline__ void ldm4(uint32_t* d, uint32_t addr) {
  asm volatile(
      "ldmatrix.sync.aligned.m8n8.x4.shared.b16 {%0,%1,%2,%3}, [%4];"
      : "=r"(d[0]), "=r"(d[1]), "=r"(d[2]), "=r"(d[3]) : "r"(addr));
}

__device__ __forceinline__ void mma_bf16(float* d, const uint32_t* a,
                                         uint32_t b0, uint32_t b1) {
  asm volatile(
      "mma.sync.aligned.m16n8k16.row.col.f32.bf16.bf16.f32 "
      "{%0,%1,%2,%3}, {%4,%5,%6,%7}, {%8,%9}, {%0,%1,%2,%3};"
      : "+f"(d[0]), "+f"(d[1]), "+f"(d[2]), "+f"(d[3])
      : "r"(a[0]), "r"(a[1]), "r"(a[2]), "r"(a[3]), "r"(b0), "r"(b1));
}

__device__ __forceinline__ void cp16(uint32_t dst, const void* src) {
  asm volatile("cp.async.cg.shared.global [%0], [%1], 16;"
               :: "r"(dst), "l"(src));
}
#define CP_COMMIT() asm volatile("cp.async.commit_group;" ::: "memory")
#define CP_WAIT1() asm volatile("cp.async.wait_group 1;" ::: "memory")
#define CP_WAIT0() asm volatile("cp.async.wait_group 0;" ::: "memory")

// Split two floats into packed bf16x2 hi + bf16x2 lo
__device__ __forceinline__ void split2(float a, float b, uint32_t& hi,
                                       uint32_t& lo) {
  __nv_bfloat16 ha = __float2bfloat16(a), hb = __float2bfloat16(b);
  __nv_bfloat162 hp = __halves2bfloat162(ha, hb);
  __nv_bfloat162 lp = __floats2bfloat162_rn(a - __bfloat162float(ha),
                                            b - __bfloat162float(hb));
  hi = *(uint32_t*)&hp;
  lo = *(uint32_t*)&lp;
}

// Reconstruct 2 floats from packed hi/lo bf16x2
__device__ __forceinline__ float2 join2(uint32_t hi, uint32_t lo) {
  __nv_bfloat162 hp = *(__nv_bfloat162*)&hi;
  __nv_bfloat162 lp = *(__nv_bfloat162*)&lo;
  float2 h = __bfloat1622float2(hp);
  float2 l = __bfloat1622float2(lp);
  return make_float2(h.x + l.x, h.y + l.y);
}

// ---------------------------------------------------------------------------
// Prep kernels
// ---------------------------------------------------------------------------
__global__ void wsplit_kernel(const float* __restrict__ W,
                              __nv_bfloat16* __restrict__ Wh,
                              __nv_bfloat16* __restrict__ Wl) {
  __shared__ float tile[32][33];
  const int bx = blockIdx.x * 32;  // n block
  const int by = blockIdx.y * 32;  // k block
  const int tx = threadIdx.x, ty = threadIdx.y;
#pragma unroll
  for (int i = 0; i < 32; i += 8)
    tile[ty + i][tx] = W[(size_t)(by + ty + i) * HID + bx + tx];
  __syncthreads();
#pragma unroll
  for (int i = 0; i < 32; i += 8) {
    int n = bx + ty + i, k = by + tx;
    float v = tile[tx][ty + i];
    __nv_bfloat16 h = __float2bfloat16(v);
    Wh[(size_t)n * HID + k] = h;
    Wl[(size_t)n * HID + k] = __float2bfloat16(v - __bfloat162float(h));
  }
}

__global__ __launch_bounds__(256) void asplit_kernel(
    const float* __restrict__ A, __nv_bfloat16* __restrict__ Ah,
    __nv_bfloat16* __restrict__ Al) {
  const int i = (blockIdx.x * 256 + threadIdx.x) * 4;
  float4 v = *(const float4*)(A + i);
  uint32_t h0, l0, h1, l1;
  split2(v.x, v.y, h0, l0);
  split2(v.z, v.w, h1, l1);
  *(uint2*)(Ah + i) = make_uint2(h0, h1);
  *(uint2*)(Al + i) = make_uint2(l0, l1);
}

// ---------------------------------------------------------------------------
// HMMA split GEMM: C = (Ah+Al)[M,K] @ (Bh+Bl)^T[N,K] + bias
// SPLIT=false: fp32 out; SPLIT=true: bf16 hi/lo out.
// ---------------------------------------------------------------------------
#define KC 64
#define TILE16K 16384          // 128 rows x 128B (KC bf16)
#define STAGEB (4 * TILE16K)   // 64KB
#define GSMEM (2 * STAGEB)     // 128KB

__device__ __forceinline__ void stage_load(
    uint32_t sm, const __nv_bfloat16* __restrict__ Ah,
    const __nv_bfloat16* __restrict__ Al, const __nv_bfloat16* __restrict__ Bh,
    const __nv_bfloat16* __restrict__ Bl, int row0, int col0, int k0, int tid) {
#pragma unroll
  for (int it = 0; it < 4; it++) {
    int idx = tid + it * 256;
    int r = idx >> 3, cb = idx & 7;
    uint32_t sw = (uint32_t)(r * 128 + ((cb ^ (r & 7)) << 4));
    size_t ga = (size_t)(row0 + r) * HID + k0 + cb * 8;
    size_t gb = (size_t)(col0 + r) * HID + k0 + cb * 8;
    cp16(sm + sw, Ah + ga);
    cp16(sm + TILE16K + sw, Al + ga);
    cp16(sm + 2 * TILE16K + sw, Bh + gb);
    cp16(sm + 3 * TILE16K + sw, Bl + gb);
  }
}

__device__ __forceinline__ void compute_stage(uint32_t sm, float acc[2][8][4],
                                              int wm0, int wn0, int lane) {
  const uint32_t smAh = sm;
  const uint32_t smAl = sm + TILE16K;
  const uint32_t smBh = sm + 2 * TILE16K;
  const uint32_t smBl = sm + 3 * TILE16K;
#pragma unroll
  for (int ks = 0; ks < 4; ks++) {
    const int cb = ks * 2 + (lane >> 4);
    uint32_t ah[2][4], al[2][4], bh[4][4], bl[4][4];
#pragma unroll
    for (int mi = 0; mi < 2; mi++) {
      int row = wm0 + mi * 16 + (lane & 15);
      uint32_t off = (uint32_t)(row * 128 + ((cb ^ (row & 7)) << 4));
      ldm4(ah[mi], smAh + off);
      ldm4(al[mi], smAl + off);
    }
#pragma unroll
    for (int ni = 0; ni < 4; ni++) {
      int row = wn0 + ni * 16 + (lane & 15);
      uint32_t off = (uint32_t)(row * 128 + ((cb ^ (row & 7)) << 4));
      ldm4(bh[ni], smBh + off);
      ldm4(bl[ni], smBl + off);
    }
#pragma unroll
    for (int mi = 0; mi < 2; mi++)
#pragma unroll
      for (int ni = 0; ni < 4; ni++) {
        mma_bf16(acc[mi][2 * ni], ah[mi], bh[ni][0], bh[ni][2]);
        mma_bf16(acc[mi][2 * ni], al[mi], bh[ni][0], bh[ni][2]);
        mma_bf16(acc[mi][2 * ni], ah[mi], bl[ni][0], bl[ni][2]);
        mma_bf16(acc[mi][2 * ni + 1], ah[mi], bh[ni][1], bh[ni][3]);
        mma_bf16(acc[mi][2 * ni + 1], al[mi], bh[ni][1], bh[ni][3]);
        mma_bf16(acc[mi][2 * ni + 1], ah[mi], bl[ni][1], bl[ni][3]);
      }
  }
}

template <bool SPLIT>
__global__ __launch_bounds__(256, 1) void gemm_hmma(
    const __nv_bfloat16* __restrict__ Ah, const __nv_bfloat16* __restrict__ Al,
    const __nv_bfloat16* __restrict__ Bh, const __nv_bfloat16* __restrict__ Bl,
    const float* __restrict__ bias, float* __restrict__ C,
    __nv_bfloat16* __restrict__ Ch, __nv_bfloat16* __restrict__ Cl) {
  extern __shared__ char smem[];
  const uint32_t sb = smem_u32(smem);
  const int tid = threadIdx.x;
  const int wid = tid >> 5, lane = tid & 31;
  const int wm0 = (wid & 3) * 32;
  const int wn0 = (wid >> 2) * 64;
  const int row0 = blockIdx.y * 128;
  const int col0 = blockIdx.x * 128;

  float acc[2][8][4];
#pragma unroll
  for (int a = 0; a < 2; a++)
#pragma unroll
    for (int b = 0; b < 8; b++)
#pragma unroll
      for (int c = 0; c < 4; c++) acc[a][b][c] = 0.f;

  stage_load(sb, Ah, Al, Bh, Bl, row0, col0, 0, tid);
  CP_COMMIT();

#pragma unroll 1
  for (int c = 0; c < HID / KC; c++) {
    if (c < HID / KC - 1) {
      stage_load(sb + ((c + 1) & 1) * STAGEB, Ah, Al, Bh, Bl, row0, col0,
                 (c + 1) * KC, tid);
      CP_COMMIT();
      CP_WAIT1();
    } else {
      CP_WAIT0();
    }
    __syncthreads();
    compute_stage(sb + (c & 1) * STAGEB, acc, wm0, wn0, lane);
    __syncthreads();
  }

  const int g = lane >> 2;
  const int q2 = (lane & 3) * 2;
#pragma unroll
  for (int mi = 0; mi < 2; mi++) {
#pragma unroll
    for (int ni = 0; ni < 8; ni++) {
      int r0 = row0 + wm0 + mi * 16 + g;
      int col = col0 + wn0 + ni * 8 + q2;
      float2 bb = *(const float2*)(bias + col);
      float v0 = acc[mi][ni][0] + bb.x, v1 = acc[mi][ni][1] + bb.y;
      float v2 = acc[mi][ni][2] + bb.x, v3 = acc[mi][ni][3] + bb.y;
      if (SPLIT) {
        uint32_t hw, lw;
        split2(v0, v1, hw, lw);
        *(uint32_t*)(Ch + (size_t)r0 * HID + col) = hw;
        *(uint32_t*)(Cl + (size_t)r0 * HID + col) = lw;
        split2(v2, v3, hw, lw);
        *(uint32_t*)(Ch + (size_t)(r0 + 8) * HID + col) = hw;
        *(uint32_t*)(Cl + (size_t)(r0 + 8) * HID + col) = lw;
      } else {
        *(float2*)(C + (size_t)r0 * HID + col) = make_float2(v0, v1);
        *(float2*)(C + (size_t)(r0 + 8) * HID + col) = make_float2(v2, v3);
      }
    }
  }
}

// ---------------------------------------------------------------------------
// BISECTION ROUND: R1-verified scalar flash attention, reading q/k/v as
// hi+lo bf16 pairs (exercises gemm_hmma<true>'s split epilogue), producing
// fp32 ctx. If this passes, the bug is inside attn_mma's core; if it fails,
// the split epilogue is guilty.
// ---------------------------------------------------------------------------
#define KV_TILE 128

__global__ __launch_bounds__(128, 2) void attn_scalar(
    const __nv_bfloat16* __restrict__ Qh, const __nv_bfloat16* __restrict__ Ql,
    const __nv_bfloat16* __restrict__ Kh, const __nv_bfloat16* __restrict__ Kl,
    const __nv_bfloat16* __restrict__ Vh, const __nv_bfloat16* __restrict__ Vl,
    float* __restrict__ Og) {
  const int h = blockIdx.y;
  const int b = blockIdx.z;
  const int tid = threadIdx.x;
  const int s = blockIdx.x * 128 + tid;

  __shared__ float Ks[KV_TILE][HDIM];
  __shared__ float Vs[KV_TILE][HDIM];

  const size_t rowQ = (size_t)(b * SEQL + s) * HID + h * HDIM;
  float q[HDIM];
#pragma unroll
  for (int d = 0; d < HDIM; d += 2) {
    uint32_t hw = *(const uint32_t*)(Qh + rowQ + d);
    uint32_t lw = *(const uint32_t*)(Ql + rowQ + d);
    float2 v = join2(hw, lw);
    q[d] = v.x;
    q[d + 1] = v.y;
  }

  const float scale = 0.125f;
  float m = -1e30f, l = 0.f;
  float o[HDIM];
#pragma unroll
  for (int d = 0; d < HDIM; d++) o[d] = 0.f;

  for (int kb = 0; kb < SEQL; kb += KV_TILE) {
    __syncthreads();
    // cooperative tile load: KV_TILE rows x 32 bf16x2-pairs each
    for (int i = tid; i < KV_TILE * (HDIM / 2); i += 128) {
      int r = i >> 5;
      int c = (i & 31) * 2;
      size_t g = (size_t)(b * SEQL + kb + r) * HID + h * HDIM + c;
      float2 kv = join2(*(const uint32_t*)(Kh + g), *(const uint32_t*)(Kl + g));
      float2 vv = join2(*(const uint32_t*)(Vh + g), *(const uint32_t*)(Vl + g));
      Ks[r][c] = kv.x;
      Ks[r][c + 1] = kv.y;
      Vs[r][c] = vv.x;
      Vs[r][c + 1] = vv.y;
    }
    __syncthreads();

#pragma unroll 1
    for (int jc = 0; jc < KV_TILE; jc += 16) {
      float sv[16];
#pragma unroll
      for (int j = 0; j < 16; j++) {
        float4 a4 = make_float4(0.f, 0.f, 0.f, 0.f);
#pragma unroll
        for (int d = 0; d < HDIM; d += 4) {
          float4 kk = *(const float4*)&Ks[jc + j][d];
          a4.x = fmaf(q[d], kk.x, a4.x);
          a4.y = fmaf(q[d + 1], kk.y, a4.y);
          a4.z = fmaf(q[d + 2], kk.z, a4.z);
          a4.w = fmaf(q[d + 3], kk.w, a4.w);
        }
        sv[j] = (a4.x + a4.y + a4.z + a4.w) * scale;
      }
      float cmax = m;
#pragma unroll
      for (int j = 0; j < 16; j++) cmax = fmaxf(cmax, sv[j]);
      float fac = __expf(m - cmax);
      m = cmax;
      l *= fac;
#pragma unroll
      for (int d = 0; d < HDIM; d++) o[d] *= fac;
#pragma unroll
      for (int j = 0; j < 16; j++) {
        float p = __expf(sv[j] - m);
        l += p;
#pragma unroll
        for (int d = 0; d < HDIM; d += 4) {
          float4 vv = *(const float4*)&Vs[jc + j][d];
          o[d]     = fmaf(p, vv.x, o[d]);
          o[d + 1] = fmaf(p, vv.y, o[d + 1]);
          o[d + 2] = fmaf(p, vv.z, o[d + 2]);
          o[d + 3] = fmaf(p, vv.w, o[d + 3]);
        }
      }
    }
  }

  const float inv = 1.f / l;
  const size_t rowO = (size_t)(b * SEQL + s) * HID + h * HDIM;
#pragma unroll
  for (int d = 0; d < HDIM; d += 4) {
    float4 t = make_float4(o[d] * inv, o[d + 1] * inv, o[d + 2] * inv,
                           o[d + 3] * inv);
    *(float4*)(Og + rowO + d) = t;
  }
}

// ---------------------------------------------------------------------------
extern "C" void kernel_launch(void* const* d_in, const int* in_sizes, int n_in,
                              void* d_out, int out_size) {
  const float* x  = (const float*)d_in[0];
  const float* Wq = (const float*)d_in[1];
  const float* bq = (const float*)d_in[2];
  const float* Wk = (const float*)d_in[3];
  const float* bk = (const float*)d_in[4];
  const float* Wv = (const float*)d_in[5];
  const float* bv = (const float*)d_in[6];
  const float* Wo = (const float*)d_in[7];
  const float* bo = (const float*)d_in[8];
  float* out = (float*)d_out;

  float* ctx;
  cudaGetSymbolAddress((void**)&ctx, g_ctx);
  __nv_bfloat16 *xh, *xl, *qh, *ql, *kh, *kl, *vh, *vl, *ch, *cl;
  cudaGetSymbolAddress((void**)&xh, g_xh);
  cudaGetSymbolAddress((void**)&xl, g_xl);
  cudaGetSymbolAddress((void**)&qh, g_qh);
  cudaGetSymbolAddress((void**)&ql, g_ql);
  cudaGetSymbolAddress((void**)&kh, g_kh);
  cudaGetSymbolAddress((void**)&kl, g_kl);
  cudaGetSymbolAddress((void**)&vh, g_vh);
  cudaGetSymbolAddress((void**)&vl, g_vl);
  cudaGetSymbolAddress((void**)&ch, g_ch);
  cudaGetSymbolAddress((void**)&cl, g_cl);
  __nv_bfloat16 *wqh, *wql, *wkh, *wkl, *wvh, *wvl, *woh, *wol;
  cudaGetSymbolAddress((void**)&wqh, g_Wqh);
  cudaGetSymbolAddress((void**)&wql, g_Wql);
  cudaGetSymbolAddress((void**)&wkh, g_Wkh);
  cudaGetSymbolAddress((void**)&wkl, g_Wkl);
  cudaGetSymbolAddress((void**)&wvh, g_Wvh);
  cudaGetSymbolAddress((void**)&wvl, g_Wvl);
  cudaGetSymbolAddress((void**)&woh, g_Woh);
  cudaGetSymbolAddress((void**)&wol, g_Wol);

  cudaFuncSetAttribute(gemm_hmma<true>,
                       cudaFuncAttributeMaxDynamicSharedMemorySize, GSMEM);
  cudaFuncSetAttribute(gemm_hmma<false>,
                       cudaFuncAttributeMaxDynamicSharedMemorySize, GSMEM);

  dim3 tb(32, 8);
  dim3 tg(32, 32);
  wsplit_kernel<<<tg, tb>>>(Wq, wqh, wql);
  wsplit_kernel<<<tg, tb>>>(Wk, wkh, wkl);
  wsplit_kernel<<<tg, tb>>>(Wv, wvh, wvl);
  wsplit_kernel<<<tg, tb>>>(Wo, woh, wol);
  asplit_kernel<<<MTOT * HID / 1024, 256>>>(x, xh, xl);

  dim3 ggrid(HID / 128, MTOT / 128);  // (8, 32)
  gemm_hmma<true><<<ggrid, 256, GSMEM>>>(xh, xl, wqh, wql, bq, nullptr, qh, ql);
  gemm_hmma<true><<<ggrid, 256, GSMEM>>>(xh, xl, wkh, wkl, bk, nullptr, kh, kl);
  gemm_hmma<true><<<ggrid, 256, GSMEM>>>(xh, xl, wvh, wvl, bv, nullptr, vh, vl);

  dim3 agrid(SEQL / 128, NHEAD, BATCH);  // (16, 16, 2)
  attn_scalar<<<agrid, 128>>>(qh, ql, kh, kl, vh, vl, ctx);

  asplit_kernel<<<MTOT * HID / 1024, 256>>>(ctx, ch, cl);
  gemm_hmma<false><<<ggrid, 256, GSMEM>>>(ch, cl, woh, wol, bo, out, nullptr,
                                          nullptr);
}

// round 9
// speedup vs baseline: 2.5325x; 2.5325x over previous
#include <cuda_runtime.h>
#include <cuda_bf16.h>
#include <math.h>
#include <stdint.h>

#define BATCH 2
#define SEQL 2048
#define HID 1024
#define NHEAD 16
#define HDIM 64
#define MTOT (BATCH * SEQL)   // 4096

// ---------------------------------------------------------------------------
// Scratch (__device__ globals; allocation-free rule)
// ---------------------------------------------------------------------------
__device__ __nv_bfloat16 g_xh[MTOT * HID], g_xl[MTOT * HID];
__device__ __nv_bfloat16 g_qh[MTOT * HID], g_ql[MTOT * HID];
__device__ __nv_bfloat16 g_kh[MTOT * HID], g_kl[MTOT * HID];
__device__ __nv_bfloat16 g_vh[MTOT * HID], g_vl[MTOT * HID];
__device__ __nv_bfloat16 g_ch[MTOT * HID], g_cl[MTOT * HID];
__device__ __nv_bfloat16 g_Wqh[HID * HID], g_Wql[HID * HID];
__device__ __nv_bfloat16 g_Wkh[HID * HID], g_Wkl[HID * HID];
__device__ __nv_bfloat16 g_Wvh[HID * HID], g_Wvl[HID * HID];
__device__ __nv_bfloat16 g_Woh[HID * HID], g_Wol[HID * HID];

// ---------------------------------------------------------------------------
// PTX helpers (arch-neutral: ldmatrix / mma.sync / cp.async only)
// ---------------------------------------------------------------------------
__device__ __forceinline__ uint32_t smem_u32(const void* p) {
  uint32_t a;
  asm("{ .reg .u64 t; cvta.to.shared.u64 t, %1; cvt.u32.u64 %0, t; }"
      : "=r"(a) : "l"(p));
  return a;
}

__device__ __forceinline__ void ldm4(uint32_t* d, uint32_t addr) {
  asm volatile(
      "ldmatrix.sync.aligned.m8n8.x4.shared.b16 {%0,%1,%2,%3}, [%4];"
      : "=r"(d[0]), "=r"(d[1]), "=r"(d[2]), "=r"(d[3]) : "r"(addr));
}

__device__ __forceinline__ void ldm4t(uint32_t* d, uint32_t addr) {
  asm volatile(
      "ldmatrix.sync.aligned.m8n8.x4.trans.shared.b16 {%0,%1,%2,%3}, [%4];"
      : "=r"(d[0]), "=r"(d[1]), "=r"(d[2]), "=r"(d[3]) : "r"(addr));
}

__device__ __forceinline__ void mma_bf16(float* d, const uint32_t* a,
                                         uint32_t b0, uint32_t b1) {
  asm volatile(
      "mma.sync.aligned.m16n8k16.row.col.f32.bf16.bf16.f32 "
      "{%0,%1,%2,%3}, {%4,%5,%6,%7}, {%8,%9}, {%0,%1,%2,%3};"
      : "+f"(d[0]), "+f"(d[1]), "+f"(d[2]), "+f"(d[3])
      : "r"(a[0]), "r"(a[1]), "r"(a[2]), "r"(a[3]), "r"(b0), "r"(b1));
}

__device__ __forceinline__ void cp16(uint32_t dst, const void* src) {
  asm volatile("cp.async.cg.shared.global [%0], [%1], 16;"
               :: "r"(dst), "l"(src));
}
#define CP_COMMIT() asm volatile("cp.async.commit_group;" ::: "memory")
#define CP_WAIT1() asm volatile("cp.async.wait_group 1;" ::: "memory")
#define CP_WAIT0() asm volatile("cp.async.wait_group 0;" ::: "memory")

__device__ __forceinline__ float ex2(float x) {
  float y;
  asm("ex2.approx.f32 %0, %1;" : "=f"(y) : "f"(x));
  return y;
}

// Split two floats into packed bf16x2 hi + bf16x2 lo
__device__ __forceinline__ void split2(float a, float b, uint32_t& hi,
                                       uint32_t& lo) {
  __nv_bfloat16 ha = __float2bfloat16(a), hb = __float2bfloat16(b);
  __nv_bfloat162 hp = __halves2bfloat162(ha, hb);
  __nv_bfloat162 lp = __floats2bfloat162_rn(a - __bfloat162float(ha),
                                            b - __bfloat162float(hb));
  hi = *(uint32_t*)&hp;
  lo = *(uint32_t*)&lp;
}

// ---------------------------------------------------------------------------
// Prep kernels
// ---------------------------------------------------------------------------
__global__ void wsplit_kernel(const float* __restrict__ W,
                              __nv_bfloat16* __restrict__ Wh,
                              __nv_bfloat16* __restrict__ Wl) {
  __shared__ float tile[32][33];
  const int bx = blockIdx.x * 32;  // n block
  const int by = blockIdx.y * 32;  // k block
  const int tx = threadIdx.x, ty = threadIdx.y;
#pragma unroll
  for (int i = 0; i < 32; i += 8)
    tile[ty + i][tx] = W[(size_t)(by + ty + i) * HID + bx + tx];
  __syncthreads();
#pragma unroll
  for (int i = 0; i < 32; i += 8) {
    int n = bx + ty + i, k = by + tx;
    float v = tile[tx][ty + i];
    __nv_bfloat16 h = __float2bfloat16(v);
    Wh[(size_t)n * HID + k] = h;
    Wl[(size_t)n * HID + k] = __float2bfloat16(v - __bfloat162float(h));
  }
}

__global__ __launch_bounds__(256) void asplit_kernel(
    const float* __restrict__ A, __nv_bfloat16* __restrict__ Ah,
    __nv_bfloat16* __restrict__ Al) {
  const int i = (blockIdx.x * 256 + threadIdx.x) * 4;
  float4 v = *(const float4*)(A + i);
  uint32_t h0, l0, h1, l1;
  split2(v.x, v.y, h0, l0);
  split2(v.z, v.w, h1, l1);
  *(uint2*)(Ah + i) = make_uint2(h0, h1);
  *(uint2*)(Al + i) = make_uint2(l0, l1);
}

// ---------------------------------------------------------------------------
// HMMA split GEMM: C = (Ah+Al)[M,K] @ (Bh+Bl)^T[N,K] + bias
// SPLIT=false: fp32 out; SPLIT=true: bf16 hi/lo out.
// ---------------------------------------------------------------------------
#define KC 64
#define TILE16K 16384          // 128 rows x 128B (KC bf16)
#define STAGEB (4 * TILE16K)   // 64KB
#define GSMEM (2 * STAGEB)     // 128KB

__device__ __forceinline__ void stage_load(
    uint32_t sm, const __nv_bfloat16* __restrict__ Ah,
    const __nv_bfloat16* __restrict__ Al, const __nv_bfloat16* __restrict__ Bh,
    const __nv_bfloat16* __restrict__ Bl, int row0, int col0, int k0, int tid) {
#pragma unroll
  for (int it = 0; it < 4; it++) {
    int idx = tid + it * 256;
    int r = idx >> 3, cb = idx & 7;
    uint32_t sw = (uint32_t)(r * 128 + ((cb ^ (r & 7)) << 4));
    size_t ga = (size_t)(row0 + r) * HID + k0 + cb * 8;
    size_t gb = (size_t)(col0 + r) * HID + k0 + cb * 8;
    cp16(sm + sw, Ah + ga);
    cp16(sm + TILE16K + sw, Al + ga);
    cp16(sm + 2 * TILE16K + sw, Bh + gb);
    cp16(sm + 3 * TILE16K + sw, Bl + gb);
  }
}

__device__ __forceinline__ void compute_stage(uint32_t sm, float acc[2][8][4],
                                              int wm0, int wn0, int lane) {
  const uint32_t smAh = sm;
  const uint32_t smAl = sm + TILE16K;
  const uint32_t smBh = sm + 2 * TILE16K;
  const uint32_t smBl = sm + 3 * TILE16K;
#pragma unroll
  for (int ks = 0; ks < 4; ks++) {
    const int cb = ks * 2 + (lane >> 4);
    uint32_t ah[2][4], al[2][4], bh[4][4], bl[4][4];
#pragma unroll
    for (int mi = 0; mi < 2; mi++) {
      int row = wm0 + mi * 16 + (lane & 15);
      uint32_t off = (uint32_t)(row * 128 + ((cb ^ (row & 7)) << 4));
      ldm4(ah[mi], smAh + off);
      ldm4(al[mi], smAl + off);
    }
#pragma unroll
    for (int ni = 0; ni < 4; ni++) {
      int row = wn0 + ni * 16 + (lane & 15);
      uint32_t off = (uint32_t)(row * 128 + ((cb ^ (row & 7)) << 4));
      ldm4(bh[ni], smBh + off);
      ldm4(bl[ni], smBl + off);
    }
#pragma unroll
    for (int mi = 0; mi < 2; mi++)
#pragma unroll
      for (int ni = 0; ni < 4; ni++) {
        mma_bf16(acc[mi][2 * ni], ah[mi], bh[ni][0], bh[ni][2]);
        mma_bf16(acc[mi][2 * ni], al[mi], bh[ni][0], bh[ni][2]);
        mma_bf16(acc[mi][2 * ni], ah[mi], bl[ni][0], bl[ni][2]);
        mma_bf16(acc[mi][2 * ni + 1], ah[mi], bh[ni][1], bh[ni][3]);
        mma_bf16(acc[mi][2 * ni + 1], al[mi], bh[ni][1], bh[ni][3]);
        mma_bf16(acc[mi][2 * ni + 1], ah[mi], bl[ni][1], bl[ni][3]);
      }
  }
}

template <bool SPLIT>
__global__ __launch_bounds__(256, 1) void gemm_hmma(
    const __nv_bfloat16* __restrict__ Ah, const __nv_bfloat16* __restrict__ Al,
    const __nv_bfloat16* __restrict__ Bh, const __nv_bfloat16* __restrict__ Bl,
    const float* __restrict__ bias, float* __restrict__ C,
    __nv_bfloat16* __restrict__ Ch, __nv_bfloat16* __restrict__ Cl) {
  extern __shared__ char smem[];
  const uint32_t sb = smem_u32(smem);
  const int tid = threadIdx.x;
  const int wid = tid >> 5, lane = tid & 31;
  const int wm0 = (wid & 3) * 32;
  const int wn0 = (wid >> 2) * 64;
  const int row0 = blockIdx.y * 128;
  const int col0 = blockIdx.x * 128;

  float acc[2][8][4];
#pragma unroll
  for (int a = 0; a < 2; a++)
#pragma unroll
    for (int b = 0; b < 8; b++)
#pragma unroll
      for (int c = 0; c < 4; c++) acc[a][b][c] = 0.f;

  stage_load(sb, Ah, Al, Bh, Bl, row0, col0, 0, tid);
  CP_COMMIT();

#pragma unroll 1
  for (int c = 0; c < HID / KC; c++) {
    if (c < HID / KC - 1) {
      stage_load(sb + ((c + 1) & 1) * STAGEB, Ah, Al, Bh, Bl, row0, col0,
                 (c + 1) * KC, tid);
      CP_COMMIT();
      CP_WAIT1();
    } else {
      CP_WAIT0();
    }
    __syncthreads();
    compute_stage(sb + (c & 1) * STAGEB, acc, wm0, wn0, lane);
    __syncthreads();
  }

  const int g = lane >> 2;
  const int q2 = (lane & 3) * 2;
#pragma unroll
  for (int mi = 0; mi < 2; mi++) {
#pragma unroll
    for (int ni = 0; ni < 8; ni++) {
      int r0 = row0 + wm0 + mi * 16 + g;
      int col = col0 + wn0 + ni * 8 + q2;
      float2 bb = *(const float2*)(bias + col);
      float v0 = acc[mi][ni][0] + bb.x, v1 = acc[mi][ni][1] + bb.y;
      float v2 = acc[mi][ni][2] + bb.x, v3 = acc[mi][ni][3] + bb.y;
      if (SPLIT) {
        uint32_t hw, lw;
        split2(v0, v1, hw, lw);
        *(uint32_t*)(Ch + (size_t)r0 * HID + col) = hw;
        *(uint32_t*)(Cl + (size_t)r0 * HID + col) = lw;
        split2(v2, v3, hw, lw);
        *(uint32_t*)(Ch + (size_t)(r0 + 8) * HID + col) = hw;
        *(uint32_t*)(Cl + (size_t)(r0 + 8) * HID + col) = lw;
      } else {
        *(float2*)(C + (size_t)r0 * HID + col) = make_float2(v0, v1);
        *(float2*)(C + (size_t)(r0 + 8) * HID + col) = make_float2(v2, v3);
      }
    }
  }
}

// ---------------------------------------------------------------------------
// Flash-MMA attention (R5 design, FIXED Q smem layout: Qh/Ql are 16KB EACH).
// Grid: (SEQ/128, NHEAD, BATCH), 256 threads (8 warps, 16 q-rows each).
// Smem: Qh 16K | Ql 16K | 2 stages x 32K (Kh,Kl,Vh,Vl) = 96KB.
// ---------------------------------------------------------------------------
#define AT_QSZ 32768
#define AT_STAGE 32768
#define AT_SMEM (AT_QSZ + 2 * AT_STAGE)  // 98304

__device__ __forceinline__ void stage_kv(
    uint32_t sm, const __nv_bfloat16* __restrict__ Kh,
    const __nv_bfloat16* __restrict__ Kl, const __nv_bfloat16* __restrict__ Vh,
    const __nv_bfloat16* __restrict__ Vl, int b, int h, int kb, int tid) {
#pragma unroll
  for (int it = 0; it < 2; it++) {
    int idx = tid + it * 256;
    int r = idx >> 3, cb = idx & 7;
    uint32_t sw = (uint32_t)(r * 128 + ((cb ^ (r & 7)) << 4));
    size_t gg = (size_t)(b * SEQL + kb + r) * HID + h * HDIM + cb * 8;
    cp16(sm + sw, Kh + gg);
    cp16(sm + 8192 + sw, Kl + gg);
    cp16(sm + 16384 + sw, Vh + gg);
    cp16(sm + 24576 + sw, Vl + gg);
  }
}

__global__ __launch_bounds__(256, 1) void attn_mma(
    const __nv_bfloat16* __restrict__ Qh, const __nv_bfloat16* __restrict__ Ql,
    const __nv_bfloat16* __restrict__ Kh, const __nv_bfloat16* __restrict__ Kl,
    const __nv_bfloat16* __restrict__ Vh, const __nv_bfloat16* __restrict__ Vl,
    __nv_bfloat16* __restrict__ Ch, __nv_bfloat16* __restrict__ Cl) {
  extern __shared__ char smem[];
  const uint32_t sQh = smem_u32(smem);
  const uint32_t sQl = sQh + 16384;   // FIX: Q tile is 16KB per component
  const uint32_t sKV = sQh + AT_QSZ;
  const int tid = threadIdx.x;
  const int wid = tid >> 5, lane = tid & 31;
  const int h = blockIdx.y, b = blockIdx.z;
  const int q0 = blockIdx.x * 128;

  // Q tile load — global row includes batch offset
#pragma unroll
  for (int it = 0; it < 4; it++) {
    int idx = tid + it * 256;
    int r = idx >> 3, cb = idx & 7;
    uint32_t sw = (uint32_t)(r * 128 + ((cb ^ (r & 7)) << 4));
    size_t gg = (size_t)(b * SEQL + q0 + r) * HID + h * HDIM + cb * 8;
    cp16(sQh + sw, Qh + gg);
    cp16(sQl + sw, Ql + gg);
  }
  CP_COMMIT();
  stage_kv(sKV, Kh, Kl, Vh, Vl, b, h, 0, tid);
  CP_COMMIT();
  CP_WAIT1();  // Q ready
  __syncthreads();

  // Q fragments (kept in regs for whole kernel)
  uint32_t qfh[4][4], qfl[4][4];
  {
    const int qrow = wid * 16 + (lane & 15);
#pragma unroll
    for (int ks = 0; ks < 4; ks++) {
      int cb = ks * 2 + (lane >> 4);
      uint32_t off = (uint32_t)(qrow * 128 + ((cb ^ (qrow & 7)) << 4));
      ldm4(qfh[ks], sQh + off);
      ldm4(qfl[ks], sQl + off);
    }
  }

  float accO[8][4];
#pragma unroll
  for (int i = 0; i < 8; i++)
#pragma unroll
    for (int j = 0; j < 4; j++) accO[i][j] = 0.f;
  float m0 = -1e30f, m1 = -1e30f, l0 = 0.f, l1 = 0.f;
  const float cs = 0.1803368801f;  // 0.125 * log2(e)

#pragma unroll 1
  for (int t = 0; t < SEQL / 64; t++) {
    if (t + 1 < SEQL / 64) {
      stage_kv(sKV + ((t + 1) & 1) * AT_STAGE, Kh, Kl, Vh, Vl, b, h,
               (t + 1) * 64, tid);
      CP_COMMIT();
      CP_WAIT1();
    } else {
      CP_WAIT0();
    }
    __syncthreads();
    const uint32_t sS = sKV + (t & 1) * AT_STAGE;

    // ---- S = Q K^T (3-term) ----
    float accS[8][4];
#pragma unroll
    for (int i = 0; i < 8; i++)
#pragma unroll
      for (int j = 0; j < 4; j++) accS[i][j] = 0.f;

#pragma unroll
    for (int ks = 0; ks < 4; ks++) {
      const int cbk = ks * 2 + (lane >> 4);
#pragma unroll
      for (int nt = 0; nt < 4; nt++) {
        int rk = nt * 16 + (lane & 15);
        uint32_t off = (uint32_t)(rk * 128 + ((cbk ^ (rk & 7)) << 4));
        uint32_t kh_[4], kl_[4];
        ldm4(kh_, sS + off);
        ldm4(kl_, sS + 8192 + off);
        mma_bf16(accS[2 * nt], qfh[ks], kh_[0], kh_[2]);
        mma_bf16(accS[2 * nt], qfl[ks], kh_[0], kh_[2]);
        mma_bf16(accS[2 * nt], qfh[ks], kl_[0], kl_[2]);
        mma_bf16(accS[2 * nt + 1], qfh[ks], kh_[1], kh_[3]);
        mma_bf16(accS[2 * nt + 1], qfl[ks], kh_[1], kh_[3]);
        mma_bf16(accS[2 * nt + 1], qfh[ks], kl_[1], kl_[3]);
      }
    }

    // ---- online softmax (rows g, g+8; scale folded into exp2 domain) ----
    float r0 = -1e30f, r1 = -1e30f;
#pragma unroll
    for (int ni = 0; ni < 8; ni++) {
      r0 = fmaxf(r0, fmaxf(accS[ni][0], accS[ni][1]));
      r1 = fmaxf(r1, fmaxf(accS[ni][2], accS[ni][3]));
    }
    r0 = fmaxf(r0, __shfl_xor_sync(0xFFFFFFFF, r0, 1));
    r0 = fmaxf(r0, __shfl_xor_sync(0xFFFFFFFF, r0, 2));
    r1 = fmaxf(r1, __shfl_xor_sync(0xFFFFFFFF, r1, 1));
    r1 = fmaxf(r1, __shfl_xor_sync(0xFFFFFFFF, r1, 2));
    float mn0 = fmaxf(m0, r0 * cs), mn1 = fmaxf(m1, r1 * cs);
    float f0 = ex2(m0 - mn0), f1 = ex2(m1 - mn1);
    m0 = mn0;
    m1 = mn1;
    l0 *= f0;
    l1 *= f1;
#pragma unroll
    for (int ni = 0; ni < 8; ni++) {
      accO[ni][0] *= f0;
      accO[ni][1] *= f0;
      accO[ni][2] *= f1;
      accO[ni][3] *= f1;
    }
#pragma unroll
    for (int ni = 0; ni < 8; ni++) {
      accS[ni][0] = ex2(fmaf(accS[ni][0], cs, -mn0));
      accS[ni][1] = ex2(fmaf(accS[ni][1], cs, -mn0));
      accS[ni][2] = ex2(fmaf(accS[ni][2], cs, -mn1));
      accS[ni][3] = ex2(fmaf(accS[ni][3], cs, -mn1));
      l0 += accS[ni][0] + accS[ni][1];
      l1 += accS[ni][2] + accS[ni][3];
    }

    // ---- PV (3-term): P frags from accS registers, V^T via ldmatrix.trans ----
#pragma unroll
    for (int ks = 0; ks < 4; ks++) {
      uint32_t aPh[4], aPl[4];
      split2(accS[2 * ks][0], accS[2 * ks][1], aPh[0], aPl[0]);
      split2(accS[2 * ks][2], accS[2 * ks][3], aPh[1], aPl[1]);
      split2(accS[2 * ks + 1][0], accS[2 * ks + 1][1], aPh[2], aPl[2]);
      split2(accS[2 * ks + 1][2], accS[2 * ks + 1][3], aPh[3], aPl[3]);
#pragma unroll
      for (int dp = 0; dp < 4; dp++) {
        int rv = ks * 16 + (lane & 15);
        int cbv = dp * 2 + (lane >> 4);
        uint32_t off = (uint32_t)(rv * 128 + ((cbv ^ (rv & 7)) << 4));
        uint32_t vh_[4], vl_[4];
        ldm4t(vh_, sS + 16384 + off);
        ldm4t(vl_, sS + 24576 + off);
        mma_bf16(accO[2 * dp], aPh, vh_[0], vh_[1]);
        mma_bf16(accO[2 * dp], aPl, vh_[0], vh_[1]);
        mma_bf16(accO[2 * dp], aPh, vl_[0], vl_[1]);
        mma_bf16(accO[2 * dp + 1], aPh, vh_[2], vh_[3]);
        mma_bf16(accO[2 * dp + 1], aPl, vh_[2], vh_[3]);
        mma_bf16(accO[2 * dp + 1], aPh, vl_[2], vl_[3]);
      }
    }
    __syncthreads();
  }

  // ---- epilogue: normalize, split, store ctx hi/lo ----
  l0 += __shfl_xor_sync(0xFFFFFFFF, l0, 1);
  l0 += __shfl_xor_sync(0xFFFFFFFF, l0, 2);
  l1 += __shfl_xor_sync(0xFFFFFFFF, l1, 1);
  l1 += __shfl_xor_sync(0xFFFFFFFF, l1, 2);
  const float i0 = 1.f / l0, i1 = 1.f / l1;
  const int ga = lane >> 2;
  const size_t row_a = (size_t)(b * SEQL + q0 + wid * 16 + ga);
  const size_t row_b = row_a + 8;
#pragma unroll
  for (int ni = 0; ni < 8; ni++) {
    int col = h * HDIM + ni * 8 + 2 * (lane & 3);
    uint32_t hw, lw;
    split2(accO[ni][0] * i0, accO[ni][1] * i0, hw, lw);
    *(uint32_t*)(Ch + row_a * HID + col) = hw;
    *(uint32_t*)(Cl + row_a * HID + col) = lw;
    split2(accO[ni][2] * i1, accO[ni][3] * i1, hw, lw);
    *(uint32_t*)(Ch + row_b * HID + col) = hw;
    *(uint32_t*)(Cl + row_b * HID + col) = lw;
  }
}

// ---------------------------------------------------------------------------
extern "C" void kernel_launch(void* const* d_in, const int* in_sizes, int n_in,
                              void* d_out, int out_size) {
  const float* x  = (const float*)d_in[0];
  const float* Wq = (const float*)d_in[1];
  const float* bq = (const float*)d_in[2];
  const float* Wk = (const float*)d_in[3];
  const float* bk = (const float*)d_in[4];
  const float* Wv = (const float*)d_in[5];
  const float* bv = (const float*)d_in[6];
  const float* Wo = (const float*)d_in[7];
  const float* bo = (const float*)d_in[8];
  float* out = (float*)d_out;

  __nv_bfloat16 *xh, *xl, *qh, *ql, *kh, *kl, *vh, *vl, *ch, *cl;
  cudaGetSymbolAddress((void**)&xh, g_xh);
  cudaGetSymbolAddress((void**)&xl, g_xl);
  cudaGetSymbolAddress((void**)&qh, g_qh);
  cudaGetSymbolAddress((void**)&ql, g_ql);
  cudaGetSymbolAddress((void**)&kh, g_kh);
  cudaGetSymbolAddress((void**)&kl, g_kl);
  cudaGetSymbolAddress((void**)&vh, g_vh);
  cudaGetSymbolAddress((void**)&vl, g_vl);
  cudaGetSymbolAddress((void**)&ch, g_ch);
  cudaGetSymbolAddress((void**)&cl, g_cl);
  __nv_bfloat16 *wqh, *wql, *wkh, *wkl, *wvh, *wvl, *woh, *wol;
  cudaGetSymbolAddress((void**)&wqh, g_Wqh);
  cudaGetSymbolAddress((void**)&wql, g_Wql);
  cudaGetSymbolAddress((void**)&wkh, g_Wkh);
  cudaGetSymbolAddress((void**)&wkl, g_Wkl);
  cudaGetSymbolAddress((void**)&wvh, g_Wvh);
  cudaGetSymbolAddress((void**)&wvl, g_Wvl);
  cudaGetSymbolAddress((void**)&woh, g_Woh);
  cudaGetSymbolAddress((void**)&wol, g_Wol);

  cudaFuncSetAttribute(gemm_hmma<true>,
                       cudaFuncAttributeMaxDynamicSharedMemorySize, GSMEM);
  cudaFuncSetAttribute(gemm_hmma<false>,
                       cudaFuncAttributeMaxDynamicSharedMemorySize, GSMEM);
  cudaFuncSetAttribute(attn_mma, cudaFuncAttributeMaxDynamicSharedMemorySize,
                       AT_SMEM);

  dim3 tb(32, 8);
  dim3 tg(32, 32);
  wsplit_kernel<<<tg, tb>>>(Wq, wqh, wql);
  wsplit_kernel<<<tg, tb>>>(Wk, wkh, wkl);
  wsplit_kernel<<<tg, tb>>>(Wv, wvh, wvl);
  wsplit_kernel<<<tg, tb>>>(Wo, woh, wol);
  asplit_kernel<<<MTOT * HID / 1024, 256>>>(x, xh, xl);

  dim3 ggrid(HID / 128, MTOT / 128);  // (8, 32)
  gemm_hmma<true><<<ggrid, 256, GSMEM>>>(xh, xl, wqh, wql, bq, nullptr, qh, ql);
  gemm_hmma<true><<<ggrid, 256, GSMEM>>>(xh, xl, wkh, wkl, bk, nullptr, kh, kl);
  gemm_hmma<true><<<ggrid, 256, GSMEM>>>(xh, xl, wvh, wvl, bv, nullptr, vh, vl);

  dim3 agrid(SEQL / 128, NHEAD, BATCH);  // (16, 16, 2)
  attn_mma<<<agrid, 256, AT_SMEM>>>(qh, ql, kh, kl, vh, vl, ch, cl);

  gemm_hmma<false><<<ggrid, 256, GSMEM>>>(ch, cl, woh, wol, bo, out, nullptr,
                                          nullptr);
}